// round 5
// baseline (speedup 1.0000x reference)
#include <cuda_runtime.h>
#include <cuda_bf16.h>

#define VOCAB 32000
#define EMB   256
#define HID   512
#define BATCH 64
#define SEQ   512
#define NB_RNN 128

typedef unsigned long long ull;

// ------------------------- device scratch (no runtime alloc) ---------------
__device__ float g_xin[(size_t)SEQ * BATCH * HID];     // [s][b][i]
__device__ float g_states[(size_t)SEQ * BATCH * HID];  // [s][b][i]
__device__ float g_feat[BATCH * 2 * HID];              // [b][1024]
__device__ unsigned int g_bar_count;                   // zero-init
__device__ unsigned int g_bar_gen;                     // zero-init

// ------------------------- packed fp32x2 helpers ---------------------------
__device__ __forceinline__ void fma2(ull& d, ull a, ull b) {
    asm("fma.rn.f32x2 %0, %1, %2, %0;" : "+l"(d) : "l"(a), "l"(b));
}
__device__ __forceinline__ float2 unpack2(ull v) {
    float lo, hi;
    asm("mov.b64 {%0, %1}, %2;" : "=f"(lo), "=f"(hi) : "l"(v));
    return make_float2(lo, hi);
}

// ------------------------- grid barrier (128 co-resident CTAs) -------------
__device__ __forceinline__ void grid_barrier_128() {
    __syncthreads();
    if (threadIdx.x == 0) {
        unsigned int g;
        asm volatile("ld.acquire.gpu.u32 %0, [%1];"
                     : "=r"(g) : "l"(&g_bar_gen) : "memory");
        __threadfence();
        unsigned int arrived = atomicAdd(&g_bar_count, 1u);
        if (arrived == NB_RNN - 1) {
            atomicExch(&g_bar_count, 0u);
            unsigned int ng = g + 1u;
            asm volatile("st.release.gpu.u32 [%0], %1;"
                         :: "l"(&g_bar_gen), "r"(ng) : "memory");
        } else {
            unsigned int cur;
            do {
                asm volatile("ld.acquire.gpu.u32 %0, [%1];"
                             : "=r"(cur) : "l"(&g_bar_gen) : "memory");
            } while (cur == g);
        }
    }
    __syncthreads();
}

// ===========================================================================
// K1: xin[s][b][i] = dot(emb[X[b,s]], W_ih[i]) + b_ih[i] + b_hh[i]
// GEMM M=32768 (row m = s*64+b), N=512, K=256. Tile 64x128, ktile 16.
// grid = (512, 4). One m-tile == one s (64 b rows).
// ===========================================================================
__global__ void __launch_bounds__(256) k1_xin(
    const int* __restrict__ X, const float* __restrict__ emb,
    const float* __restrict__ W_ih, const float* __restrict__ b_ih,
    const float* __restrict__ b_hh)
{
    __shared__ int   rsh[64];
    __shared__ float As[16 * 64];   // [k][m]
    __shared__ float Bs[16 * 128];  // [k][n]
    const int t  = threadIdx.x;
    const int mt = blockIdx.x;            // == s
    const int n0 = blockIdx.y * 128;
    if (t < 64) rsh[t] = X[(size_t)t * SEQ + mt];

    const int tx = t & 31, ty = t >> 5;
    const int ml = t >> 2, kq = (t & 3) * 4;
    const int vb = t >> 1, k8 = (t & 1) * 8;

    float acc[8][4];
#pragma unroll
    for (int r = 0; r < 8; r++)
#pragma unroll
        for (int c = 0; c < 4; c++) acc[r][c] = 0.f;

    __syncthreads();
    const int arow = rsh[ml];

    for (int k0 = 0; k0 < EMB; k0 += 16) {
        float4 av = *(const float4*)&emb[(size_t)arow * EMB + k0 + kq];
        As[(kq + 0) * 64 + ml] = av.x;
        As[(kq + 1) * 64 + ml] = av.y;
        As[(kq + 2) * 64 + ml] = av.z;
        As[(kq + 3) * 64 + ml] = av.w;
#pragma unroll
        for (int h = 0; h < 2; h++) {
            float4 bv = *(const float4*)&W_ih[(size_t)(n0 + vb) * EMB + k0 + k8 + 4 * h];
            Bs[(k8 + 4 * h + 0) * 128 + vb] = bv.x;
            Bs[(k8 + 4 * h + 1) * 128 + vb] = bv.y;
            Bs[(k8 + 4 * h + 2) * 128 + vb] = bv.z;
            Bs[(k8 + 4 * h + 3) * 128 + vb] = bv.w;
        }
        __syncthreads();
#pragma unroll
        for (int kk = 0; kk < 16; kk++) {
            float4 A0 = *(const float4*)&As[kk * 64 + ty * 8];
            float4 A1 = *(const float4*)&As[kk * 64 + ty * 8 + 4];
            float4 Wv = *(const float4*)&Bs[kk * 128 + tx * 4];
            float a[8] = {A0.x, A0.y, A0.z, A0.w, A1.x, A1.y, A1.z, A1.w};
            float wv[4] = {Wv.x, Wv.y, Wv.z, Wv.w};
#pragma unroll
            for (int r = 0; r < 8; r++)
#pragma unroll
                for (int c = 0; c < 4; c++)
                    acc[r][c] = fmaf(a[r], wv[c], acc[r][c]);
        }
        __syncthreads();
    }

    const int nbase = n0 + tx * 4;
    float bias[4];
#pragma unroll
    for (int c = 0; c < 4; c++) bias[c] = b_ih[nbase + c] + b_hh[nbase + c];
#pragma unroll
    for (int r = 0; r < 8; r++) {
        int bl = ty * 8 + r;  // b (since m-tile == s)
        float4 o;
        o.x = acc[r][0] + bias[0];
        o.y = acc[r][1] + bias[1];
        o.z = acc[r][2] + bias[2];
        o.w = acc[r][3] + bias[3];
        *(float4*)&g_xin[((size_t)mt * BATCH + bl) * HID + nbase] = o;
    }
}

// ===========================================================================
// K2: persistent RNN. grid = 128 = 8 batch-groups x 16 i-groups.
// CTA (bg, ig): outputs h[b][i] for b in [bg*8, +8), i in [ig*32, +32).
// 256 threads: warp w = j-slice (w*64..w*64+63), lane = i_local.
// W_hh slice (32 x 512, pad 514) cached in smem for all steps.
// ===========================================================================
#define WPAD 514
extern __shared__ float k2smem[];

__global__ void __launch_bounds__(256, 1) k2_rnn(const float* __restrict__ W_hh)
{
    float* Wsh = k2smem;                    // 32 * 514
    float* hsh = k2smem + 32 * WPAD;        // 8 * 512
    float* red = hsh + 8 * 512;             // 8 * 8 * 32

    const int t    = threadIdx.x;
    const int lane = t & 31;
    const int w    = t >> 5;
    const int bg   = blockIdx.x >> 4;
    const int ig   = blockIdx.x & 15;

    // load W_hh slice once
    for (int q = 0; q < 64; q++) {
        int lin = q * 256 + t;
        int il = lin >> 9, j = lin & 511;
        Wsh[il * WPAD + j] = W_hh[(size_t)(ig * 32 + il) * HID + j];
    }
    __syncthreads();

    const int bglob = bg * 8 + w;           // reduce-phase b (t>>5)
    const int iglob = ig * 32 + lane;
    const ull* wp = (const ull*)&Wsh[lane * WPAD + w * 64];

    for (int s = 0; s < SEQ; s++) {
        float dot = 0.f;
        if (s > 0) {
            // stage h(s-1) for this CTA's 8 batches: 4096 floats
            const float4* src =
                (const float4*)&g_states[((size_t)(s - 1) * BATCH + bg * 8) * HID];
            float4* dst = (float4*)hsh;
#pragma unroll
            for (int q = 0; q < 4; q++) dst[q * 256 + t] = src[q * 256 + t];
            __syncthreads();

            ull acc[8];
#pragma unroll
            for (int b = 0; b < 8; b++) acc[b] = 0ull;
#pragma unroll 8
            for (int jj = 0; jj < 32; jj++) {
                ull wv = wp[jj];
#pragma unroll
                for (int b = 0; b < 8; b++) {
                    ull hv = ((const ull*)&hsh[b * 512 + w * 64])[jj];
                    fma2(acc[b], wv, hv);
                }
            }
#pragma unroll
            for (int b = 0; b < 8; b++) {
                float2 p = unpack2(acc[b]);
                red[w * 256 + b * 32 + lane] = p.x + p.y;
            }
            __syncthreads();
#pragma unroll
            for (int ws = 0; ws < 8; ws++)
                dot += red[ws * 256 + w * 32 + lane];
        }
        float val = g_xin[((size_t)s * BATCH + bglob) * HID + iglob] + dot;
        float h = tanhf(val);
        g_states[((size_t)s * BATCH + bglob) * HID + iglob] = h;
        grid_barrier_128();
    }
}

// ===========================================================================
// K3: attention + feat. One CTA per batch b, 512 threads.
// ===========================================================================
__global__ void __launch_bounds__(512) k3_attn()
{
    __shared__ float lsh[512];
    __shared__ float ash[512];
    __shared__ float red[16];
    const int b = blockIdx.x;
    const int t = threadIdx.x;
    const int lane = t & 31, wid = t >> 5;

    lsh[t] = g_states[((size_t)(SEQ - 1) * BATCH + b) * HID + t];
    __syncthreads();

    // scores[s] = dot(h_s, last), s in [0, 510]
    for (int s = wid; s < SEQ - 1; s += 16) {
        const float* hs = &g_states[((size_t)s * BATCH + b) * HID];
        float p = 0.f;
#pragma unroll
        for (int m = 0; m < 16; m++)
            p = fmaf(hs[lane + 32 * m], lsh[lane + 32 * m], p);
#pragma unroll
        for (int o = 16; o > 0; o >>= 1) p += __shfl_down_sync(0xffffffffu, p, o);
        if (lane == 0) ash[s] = p;
    }
    __syncthreads();

    // softmax over ash[0..510]
    float v = (t < SEQ - 1) ? ash[t] : -3.0e38f;
    float mx = v;
#pragma unroll
    for (int o = 16; o > 0; o >>= 1) mx = fmaxf(mx, __shfl_xor_sync(0xffffffffu, mx, o));
    if (lane == 0) red[wid] = mx;
    __syncthreads();
    float m2 = red[0];
#pragma unroll
    for (int i = 1; i < 16; i++) m2 = fmaxf(m2, red[i]);
    __syncthreads();

    float e = (t < SEQ - 1) ? __expf(v - m2) : 0.f;
    float sm = e;
#pragma unroll
    for (int o = 16; o > 0; o >>= 1) sm += __shfl_xor_sync(0xffffffffu, sm, o);
    if (lane == 0) red[wid] = sm;
    __syncthreads();
    float tot = 0.f;
#pragma unroll
    for (int i = 0; i < 16; i++) tot += red[i];
    float inv = 1.f / tot;
    __syncthreads();
    if (t < SEQ - 1) ash[t] = e * inv;
    __syncthreads();

    // ctx[i] = sum_s attn[s] * h_s[i]
    float ctx = 0.f;
#pragma unroll 4
    for (int s = 0; s < SEQ - 1; s++)
        ctx = fmaf(ash[s], g_states[((size_t)s * BATCH + b) * HID + t], ctx);

    g_feat[b * 1024 + t]       = ctx;
    g_feat[b * 1024 + 512 + t] = lsh[t];
}

// ===========================================================================
// K4: out[b][v] = dot(feat[b], W[v]) + bias[v]. M=64, N=32000, K=1024.
// Tile 64x128, ktile 16. grid = 250.
// ===========================================================================
__global__ void __launch_bounds__(256) k4_out(
    const float* __restrict__ W, const float* __restrict__ bias,
    float* __restrict__ out)
{
    __shared__ float As[16 * 64];
    __shared__ float Bs[16 * 128];
    const int t  = threadIdx.x;
    const int n0 = blockIdx.x * 128;
    const int tx = t & 31, ty = t >> 5;
    const int ml = t >> 2, kq = (t & 3) * 4;
    const int vb = t >> 1, k8 = (t & 1) * 8;

    float acc[8][4];
#pragma unroll
    for (int r = 0; r < 8; r++)
#pragma unroll
        for (int c = 0; c < 4; c++) acc[r][c] = 0.f;

    for (int k0 = 0; k0 < 2 * HID; k0 += 16) {
        float4 av = *(const float4*)&g_feat[(size_t)ml * 1024 + k0 + kq];
        As[(kq + 0) * 64 + ml] = av.x;
        As[(kq + 1) * 64 + ml] = av.y;
        As[(kq + 2) * 64 + ml] = av.z;
        As[(kq + 3) * 64 + ml] = av.w;
#pragma unroll
        for (int h = 0; h < 2; h++) {
            float4 bv = *(const float4*)&W[(size_t)(n0 + vb) * 1024 + k0 + k8 + 4 * h];
            Bs[(k8 + 4 * h + 0) * 128 + vb] = bv.x;
            Bs[(k8 + 4 * h + 1) * 128 + vb] = bv.y;
            Bs[(k8 + 4 * h + 2) * 128 + vb] = bv.z;
            Bs[(k8 + 4 * h + 3) * 128 + vb] = bv.w;
        }
        __syncthreads();
#pragma unroll
        for (int kk = 0; kk < 16; kk++) {
            float4 A0 = *(const float4*)&As[kk * 64 + ty * 8];
            float4 A1 = *(const float4*)&As[kk * 64 + ty * 8 + 4];
            float4 Wv = *(const float4*)&Bs[kk * 128 + tx * 4];
            float a[8] = {A0.x, A0.y, A0.z, A0.w, A1.x, A1.y, A1.z, A1.w};
            float wv[4] = {Wv.x, Wv.y, Wv.z, Wv.w};
#pragma unroll
            for (int r = 0; r < 8; r++)
#pragma unroll
                for (int c = 0; c < 4; c++)
                    acc[r][c] = fmaf(a[r], wv[c], acc[r][c]);
        }
        __syncthreads();
    }

    const int nbase = n0 + tx * 4;
    float bv0 = bias[nbase + 0], bv1 = bias[nbase + 1];
    float bv2 = bias[nbase + 2], bv3 = bias[nbase + 3];
#pragma unroll
    for (int r = 0; r < 8; r++) {
        int bb = ty * 8 + r;
        float4 o;
        o.x = acc[r][0] + bv0;
        o.y = acc[r][1] + bv1;
        o.z = acc[r][2] + bv2;
        o.w = acc[r][3] + bv3;
        *(float4*)&out[(size_t)bb * VOCAB + nbase] = o;
    }
}

// ===========================================================================
extern "C" void kernel_launch(void* const* d_in, const int* in_sizes, int n_in,
                              void* d_out, int out_size) {
    (void)in_sizes; (void)n_in; (void)out_size;
    const int*   X    = (const int*)d_in[0];
    const float* emb  = (const float*)d_in[1];
    const float* W_ih = (const float*)d_in[2];
    const float* W_hh = (const float*)d_in[3];
    const float* b_ih = (const float*)d_in[4];
    const float* b_hh = (const float*)d_in[5];
    const float* W    = (const float*)d_in[6];
    const float* bias = (const float*)d_in[7];
    float* out = (float*)d_out;

    k1_xin<<<dim3(SEQ, 4), 256>>>(X, emb, W_ih, b_ih, b_hh);

    const int smem2 = (32 * WPAD + 8 * 512 + 8 * 8 * 32) * (int)sizeof(float);
    cudaFuncSetAttribute(k2_rnn, cudaFuncAttributeMaxDynamicSharedMemorySize, smem2);
    k2_rnn<<<NB_RNN, 256, smem2>>>(W_hh);

    k3_attn<<<BATCH, 512>>>();
    k4_out<<<VOCAB / 128, 256>>>(W, bias, out);
}

// round 6
// speedup vs baseline: 1.0003x; 1.0003x over previous
#include <cuda_runtime.h>
#include <cuda_bf16.h>

#define VOCAB 32000
#define EMB   256
#define HID   512
#define BATCH 64
#define SEQ   512

typedef unsigned long long ull;

// ------------------------- device scratch (no runtime alloc) ---------------
__device__ float g_xin[(size_t)SEQ * BATCH * HID];     // [s][b][i]
__device__ float g_states[(size_t)SEQ * BATCH * HID];  // [s][b][i]
__device__ float g_feat[BATCH * 2 * HID];              // [b][1024]

// ------------------------- packed fp32x2 helpers ---------------------------
__device__ __forceinline__ void fma2(ull& d, ull a, ull b) {
    asm("fma.rn.f32x2 %0, %1, %2, %0;" : "+l"(d) : "l"(a), "l"(b));
}
__device__ __forceinline__ float2 unpack2(ull v) {
    float lo, hi;
    asm("mov.b64 {%0, %1}, %2;" : "=f"(lo), "=f"(hi) : "l"(v));
    return make_float2(lo, hi);
}
__device__ __forceinline__ ull dup2(float x) {
    ull r;
    asm("mov.b64 %0, {%1, %1};" : "=l"(r) : "f"(x));
    return r;
}
__device__ __forceinline__ unsigned smem_u32(const void* p) {
    unsigned a;
    asm("{ .reg .u64 t; cvta.to.shared.u64 t, %1; cvt.u32.u64 %0, t; }"
        : "=r"(a) : "l"(p));
    return a;
}

// ===========================================================================
// K1: xin[s][b][i] = dot(emb[X[b,s]], W_ih[i]) + b_ih[i] + b_hh[i]
// GEMM M=32768 (m = s*64+b), N=512, K=256. Tile 64x128, ktile 16.
// Inner loop packed fp32x2 (pairs over adjacent m-rows).
// ===========================================================================
__global__ void __launch_bounds__(256) k1_xin(
    const int* __restrict__ X, const float* __restrict__ emb,
    const float* __restrict__ W_ih, const float* __restrict__ b_ih,
    const float* __restrict__ b_hh)
{
    __shared__ int rsh[64];
    __shared__ __align__(16) float As[16 * 64];   // [k][m]
    __shared__ __align__(16) float Bs[16 * 128];  // [k][n]
    const int t  = threadIdx.x;
    const int mt = blockIdx.x;            // == s
    const int n0 = blockIdx.y * 128;
    if (t < 64) rsh[t] = X[(size_t)t * SEQ + mt];

    const int tx = t & 31, ty = t >> 5;
    const int ml = t >> 2, kq = (t & 3) * 4;
    const int vb = t >> 1, k8 = (t & 1) * 8;

    ull acc2[4][4];   // [row-pair][n] ; lo = row 2rp, hi = row 2rp+1
#pragma unroll
    for (int rp = 0; rp < 4; rp++)
#pragma unroll
        for (int c = 0; c < 4; c++) acc2[rp][c] = 0ull;

    __syncthreads();
    const int arow = rsh[ml];

    for (int k0 = 0; k0 < EMB; k0 += 16) {
        float4 av = *(const float4*)&emb[(size_t)arow * EMB + k0 + kq];
        As[(kq + 0) * 64 + ml] = av.x;
        As[(kq + 1) * 64 + ml] = av.y;
        As[(kq + 2) * 64 + ml] = av.z;
        As[(kq + 3) * 64 + ml] = av.w;
#pragma unroll
        for (int h = 0; h < 2; h++) {
            float4 bv = *(const float4*)&W_ih[(size_t)(n0 + vb) * EMB + k0 + k8 + 4 * h];
            Bs[(k8 + 4 * h + 0) * 128 + vb] = bv.x;
            Bs[(k8 + 4 * h + 1) * 128 + vb] = bv.y;
            Bs[(k8 + 4 * h + 2) * 128 + vb] = bv.z;
            Bs[(k8 + 4 * h + 3) * 128 + vb] = bv.w;
        }
        __syncthreads();
#pragma unroll
        for (int kk = 0; kk < 16; kk++) {
            const ull* ap = (const ull*)&As[kk * 64 + ty * 8];
            ull a0 = ap[0], a1 = ap[1], a2 = ap[2], a3 = ap[3];
            float4 Wv = *(const float4*)&Bs[kk * 128 + tx * 4];
            ull wd[4] = {dup2(Wv.x), dup2(Wv.y), dup2(Wv.z), dup2(Wv.w)};
#pragma unroll
            for (int c = 0; c < 4; c++) {
                fma2(acc2[0][c], a0, wd[c]);
                fma2(acc2[1][c], a1, wd[c]);
                fma2(acc2[2][c], a2, wd[c]);
                fma2(acc2[3][c], a3, wd[c]);
            }
        }
        __syncthreads();
    }

    const int nbase = n0 + tx * 4;
    float bias[4];
#pragma unroll
    for (int c = 0; c < 4; c++) bias[c] = b_ih[nbase + c] + b_hh[nbase + c];
#pragma unroll
    for (int rp = 0; rp < 4; rp++) {
        float2 p0 = unpack2(acc2[rp][0]);
        float2 p1 = unpack2(acc2[rp][1]);
        float2 p2 = unpack2(acc2[rp][2]);
        float2 p3 = unpack2(acc2[rp][3]);
        int bl0 = ty * 8 + 2 * rp;
        float4 o0, o1;
        o0.x = p0.x + bias[0]; o0.y = p1.x + bias[1];
        o0.z = p2.x + bias[2]; o0.w = p3.x + bias[3];
        o1.x = p0.y + bias[0]; o1.y = p1.y + bias[1];
        o1.z = p2.y + bias[2]; o1.w = p3.y + bias[3];
        *(float4*)&g_xin[((size_t)mt * BATCH + bl0) * HID + nbase]     = o0;
        *(float4*)&g_xin[((size_t)mt * BATCH + bl0 + 1) * HID + nbase] = o1;
    }
}

// ===========================================================================
// K2: persistent clustered RNN. 16 independent clusters x 8 CTAs = 128 CTAs.
// Cluster cg owns batches [cg*4, +4). CTA rank owns i-rows [rank*64, +64)
// of W_hh, cached in smem (pitch 514 -> conflict-free strided LDS.64).
// Per step: 8-way j-split compute + smem reduce; result h pushed to all 8
// cluster CTAs' parity-buffered h arrays via st.shared::cluster; then
// barrier.cluster. NO global barrier, NO global h on the critical path.
// ===========================================================================
#define PITW 514
extern __shared__ float k2smem[];

__global__ void __launch_bounds__(256, 1) __cluster_dims__(8, 1, 1)
k2_rnn(const float* __restrict__ W_hh)
{
    float* Wsh  = k2smem;                       // 64 * 514
    float* hbuf = k2smem + 64 * PITW;           // 2 * 4 * 512 (parity, b, j)
    float* red  = hbuf + 2 * 4 * 512;           // 8 * 256

    const int t = threadIdx.x;
    unsigned rank;
    asm("mov.u32 %0, %%cluster_ctarank;" : "=r"(rank));
    const int cg = blockIdx.x >> 3;
    const int b0 = cg * 4;

    // ---- load own W_hh slice once (64 rows) ----
    {
        const float4* src = (const float4*)&W_hh[(size_t)(rank * 64) * HID];
#pragma unroll
        for (int q = 0; q < 32; q++) {
            int lin = q * 256 + t;       // float4 index in 64x512
            int row = lin >> 7;          // 128 float4 per row
            int col = (lin & 127) * 4;
            float4 v = src[lin];
            float* d = &Wsh[row * PITW + col];
            d[0] = v.x; d[1] = v.y; d[2] = v.z; d[3] = v.w;
        }
    }

    // ---- roles ----
    const int ip   = t & 31;            // i-pair base: rows ip, ip+32 (local)
    const int jseg = t >> 5;            // 8 j-segments of 64
    const int ob   = t >> 6;            // output batch (0..3)
    const int oi   = t & 63;            // output i (local)
    const int iglob = (int)rank * 64 + oi;

    // peer base addresses of hbuf (DSMEM), computed once
    unsigned hb32 = smem_u32(hbuf);
    unsigned peer[8];
#pragma unroll
    for (int r = 0; r < 8; r++)
        asm("mapa.shared::cluster.u32 %0, %1, %2;"
            : "=r"(peer[r]) : "r"(hb32), "r"(r));

    const ull* wp0 = (const ull*)&Wsh[ip * PITW + jseg * 64];
    const ull* wp1 = (const ull*)&Wsh[(ip + 32) * PITW + jseg * 64];

    for (int s = 0; s < SEQ; s++) {
        // prefetch xin early (hidden behind compute)
        float xv = __ldg(&g_xin[((size_t)s * BATCH + b0 + ob) * HID + iglob]);

        float dot = 0.f;
        if (s > 0) {
            const float* hb = hbuf + ((s - 1) & 1) * 2048;
            const ull* hp0 = (const ull*)&hb[0 * 512 + jseg * 64];
            const ull* hp1 = (const ull*)&hb[1 * 512 + jseg * 64];
            const ull* hp2 = (const ull*)&hb[2 * 512 + jseg * 64];
            const ull* hp3 = (const ull*)&hb[3 * 512 + jseg * 64];
            ull acc[8];
#pragma unroll
            for (int q = 0; q < 8; q++) acc[q] = 0ull;
#pragma unroll 8
            for (int jj = 0; jj < 32; jj++) {
                ull w0 = wp0[jj];
                ull w1 = wp1[jj];
                ull h0 = hp0[jj], h1 = hp1[jj], h2 = hp2[jj], h3 = hp3[jj];
                fma2(acc[0], w0, h0); fma2(acc[4], w1, h0);
                fma2(acc[1], w0, h1); fma2(acc[5], w1, h1);
                fma2(acc[2], w0, h2); fma2(acc[6], w1, h2);
                fma2(acc[3], w0, h3); fma2(acc[7], w1, h3);
            }
#pragma unroll
            for (int b4 = 0; b4 < 4; b4++) {
                float2 pa = unpack2(acc[b4]);
                float2 pb = unpack2(acc[4 + b4]);
                red[jseg * 256 + b4 * 64 + ip]      = pa.x + pa.y;
                red[jseg * 256 + b4 * 64 + ip + 32] = pb.x + pb.y;
            }
            __syncthreads();
#pragma unroll
            for (int q = 0; q < 8; q++)
                dot += red[q * 256 + t];
        }

        float h = tanhf(xv + dot);

        // push h to every cluster CTA's parity buffer (incl. self)
        unsigned boff = (unsigned)(((s & 1) * 2048 + ob * 512 + iglob) * 4);
#pragma unroll
        for (int r = 0; r < 8; r++)
            asm volatile("st.shared::cluster.f32 [%0], %1;"
                         :: "r"(peer[r] + boff), "f"(h) : "memory");

        // record for attention pass (off critical path)
        g_states[((size_t)s * BATCH + b0 + ob) * HID + iglob] = h;

        asm volatile("barrier.cluster.arrive.aligned;" ::: "memory");
        asm volatile("barrier.cluster.wait.aligned;" ::: "memory");
    }
}

// ===========================================================================
// K3: attention + feat. One CTA per batch b, 512 threads.
// ===========================================================================
__global__ void __launch_bounds__(512) k3_attn()
{
    __shared__ float lsh[512];
    __shared__ float ash[512];
    __shared__ float red[16];
    const int b = blockIdx.x;
    const int t = threadIdx.x;
    const int lane = t & 31, wid = t >> 5;

    lsh[t] = g_states[((size_t)(SEQ - 1) * BATCH + b) * HID + t];
    __syncthreads();

    for (int s = wid; s < SEQ - 1; s += 16) {
        const float* hs = &g_states[((size_t)s * BATCH + b) * HID];
        float p = 0.f;
#pragma unroll
        for (int m = 0; m < 16; m++)
            p = fmaf(hs[lane + 32 * m], lsh[lane + 32 * m], p);
#pragma unroll
        for (int o = 16; o > 0; o >>= 1) p += __shfl_down_sync(0xffffffffu, p, o);
        if (lane == 0) ash[s] = p;
    }
    __syncthreads();

    float v = (t < SEQ - 1) ? ash[t] : -3.0e38f;
    float mx = v;
#pragma unroll
    for (int o = 16; o > 0; o >>= 1) mx = fmaxf(mx, __shfl_xor_sync(0xffffffffu, mx, o));
    if (lane == 0) red[wid] = mx;
    __syncthreads();
    float m2 = red[0];
#pragma unroll
    for (int i = 1; i < 16; i++) m2 = fmaxf(m2, red[i]);
    __syncthreads();

    float e = (t < SEQ - 1) ? __expf(v - m2) : 0.f;
    float sm = e;
#pragma unroll
    for (int o = 16; o > 0; o >>= 1) sm += __shfl_xor_sync(0xffffffffu, sm, o);
    if (lane == 0) red[wid] = sm;
    __syncthreads();
    float tot = 0.f;
#pragma unroll
    for (int i = 0; i < 16; i++) tot += red[i];
    float inv = 1.f / tot;
    __syncthreads();
    if (t < SEQ - 1) ash[t] = e * inv;
    __syncthreads();

    float ctx = 0.f;
#pragma unroll 4
    for (int s = 0; s < SEQ - 1; s++)
        ctx = fmaf(ash[s], g_states[((size_t)s * BATCH + b) * HID + t], ctx);

    g_feat[b * 1024 + t]       = ctx;
    g_feat[b * 1024 + 512 + t] = lsh[t];
}

// ===========================================================================
// K4: out[b][v] = dot(feat[b], W[v]) + bias[v]. M=64, N=32000, K=1024.
// Tile 64x128, ktile 16, packed fp32x2 inner loop.
// ===========================================================================
__global__ void __launch_bounds__(256) k4_out(
    const float* __restrict__ W, const float* __restrict__ bias,
    float* __restrict__ out)
{
    __shared__ __align__(16) float As[16 * 64];
    __shared__ __align__(16) float Bs[16 * 128];
    const int t  = threadIdx.x;
    const int n0 = blockIdx.x * 128;
    const int tx = t & 31, ty = t >> 5;
    const int ml = t >> 2, kq = (t & 3) * 4;
    const int vb = t >> 1, k8 = (t & 1) * 8;

    ull acc2[4][4];
#pragma unroll
    for (int rp = 0; rp < 4; rp++)
#pragma unroll
        for (int c = 0; c < 4; c++) acc2[rp][c] = 0ull;

    for (int k0 = 0; k0 < 2 * HID; k0 += 16) {
        float4 av = *(const float4*)&g_feat[(size_t)ml * 1024 + k0 + kq];
        As[(kq + 0) * 64 + ml] = av.x;
        As[(kq + 1) * 64 + ml] = av.y;
        As[(kq + 2) * 64 + ml] = av.z;
        As[(kq + 3) * 64 + ml] = av.w;
#pragma unroll
        for (int h = 0; h < 2; h++) {
            float4 bv = *(const float4*)&W[(size_t)(n0 + vb) * 1024 + k0 + k8 + 4 * h];
            Bs[(k8 + 4 * h + 0) * 128 + vb] = bv.x;
            Bs[(k8 + 4 * h + 1) * 128 + vb] = bv.y;
            Bs[(k8 + 4 * h + 2) * 128 + vb] = bv.z;
            Bs[(k8 + 4 * h + 3) * 128 + vb] = bv.w;
        }
        __syncthreads();
#pragma unroll
        for (int kk = 0; kk < 16; kk++) {
            const ull* ap = (const ull*)&As[kk * 64 + ty * 8];
            ull a0 = ap[0], a1 = ap[1], a2 = ap[2], a3 = ap[3];
            float4 Wv = *(const float4*)&Bs[kk * 128 + tx * 4];
            ull wd[4] = {dup2(Wv.x), dup2(Wv.y), dup2(Wv.z), dup2(Wv.w)};
#pragma unroll
            for (int c = 0; c < 4; c++) {
                fma2(acc2[0][c], a0, wd[c]);
                fma2(acc2[1][c], a1, wd[c]);
                fma2(acc2[2][c], a2, wd[c]);
                fma2(acc2[3][c], a3, wd[c]);
            }
        }
        __syncthreads();
    }

    const int nbase = n0 + tx * 4;
    float bv0 = bias[nbase + 0], bv1 = bias[nbase + 1];
    float bv2 = bias[nbase + 2], bv3 = bias[nbase + 3];
#pragma unroll
    for (int rp = 0; rp < 4; rp++) {
        float2 p0 = unpack2(acc2[rp][0]);
        float2 p1 = unpack2(acc2[rp][1]);
        float2 p2 = unpack2(acc2[rp][2]);
        float2 p3 = unpack2(acc2[rp][3]);
        int bb0 = ty * 8 + 2 * rp;
        float4 o0, o1;
        o0.x = p0.x + bv0; o0.y = p1.x + bv1; o0.z = p2.x + bv2; o0.w = p3.x + bv3;
        o1.x = p0.y + bv0; o1.y = p1.y + bv1; o1.z = p2.y + bv2; o1.w = p3.y + bv3;
        *(float4*)&out[(size_t)bb0 * VOCAB + nbase]       = o0;
        *(float4*)&out[(size_t)(bb0 + 1) * VOCAB + nbase] = o1;
    }
}

// ===========================================================================
extern "C" void kernel_launch(void* const* d_in, const int* in_sizes, int n_in,
                              void* d_out, int out_size) {
    (void)in_sizes; (void)n_in; (void)out_size;
    const int*   X    = (const int*)d_in[0];
    const float* emb  = (const float*)d_in[1];
    const float* W_ih = (const float*)d_in[2];
    const float* W_hh = (const float*)d_in[3];
    const float* b_ih = (const float*)d_in[4];
    const float* b_hh = (const float*)d_in[5];
    const float* W    = (const float*)d_in[6];
    const float* bias = (const float*)d_in[7];
    float* out = (float*)d_out;

    k1_xin<<<dim3(SEQ, 4), 256>>>(X, emb, W_ih, b_ih, b_hh);

    const int smem2 = (64 * PITW + 2 * 4 * 512 + 8 * 256) * (int)sizeof(float);
    cudaFuncSetAttribute(k2_rnn, cudaFuncAttributeMaxDynamicSharedMemorySize, smem2);
    k2_rnn<<<128, 256, smem2>>>(W_hh);

    k3_attn<<<BATCH, 512>>>();
    k4_out<<<VOCAB / 128, 256>>>(W, bias, out);
}

// round 7
// speedup vs baseline: 1.2871x; 1.2868x over previous
#include <cuda_runtime.h>
#include <cuda_bf16.h>

#define VOCAB 32000
#define EMB   256
#define HID   512
#define BATCH 64
#define SEQ   512

typedef unsigned long long ull;

// ------------------------- device scratch (no runtime alloc) ---------------
__device__ float g_xin[(size_t)SEQ * BATCH * HID];     // [s][b][i]
__device__ float g_states[(size_t)SEQ * BATCH * HID];  // [s][b][i]
__device__ float g_feat[BATCH * 2 * HID];              // [b][1024]

// ------------------------- packed fp32x2 helpers ---------------------------
__device__ __forceinline__ void fma2(ull& d, ull a, ull b) {
    asm("fma.rn.f32x2 %0, %1, %2, %0;" : "+l"(d) : "l"(a), "l"(b));
}
__device__ __forceinline__ float2 unpack2(ull v) {
    float lo, hi;
    asm("mov.b64 {%0, %1}, %2;" : "=f"(lo), "=f"(hi) : "l"(v));
    return make_float2(lo, hi);
}
__device__ __forceinline__ ull dup2(float x) {
    ull r;
    asm("mov.b64 %0, {%1, %1};" : "=l"(r) : "f"(x));
    return r;
}
__device__ __forceinline__ unsigned smem_u32(const void* p) {
    unsigned a;
    asm("{ .reg .u64 t; cvta.to.shared.u64 t, %1; cvt.u32.u64 %0, t; }"
        : "=r"(a) : "l"(p));
    return a;
}

// ===========================================================================
// K1: xin[s][b][i] = dot(emb[X[b,s]], W_ih[i]) + b_ih[i] + b_hh[i]
// GEMM M=32768 (m = s*64+b), N=512, K=256. Tile 64x128, ktile 16.
// ===========================================================================
__global__ void __launch_bounds__(256) k1_xin(
    const int* __restrict__ X, const float* __restrict__ emb,
    const float* __restrict__ W_ih, const float* __restrict__ b_ih,
    const float* __restrict__ b_hh)
{
    __shared__ int rsh[64];
    __shared__ __align__(16) float As[16 * 64];   // [k][m]
    __shared__ __align__(16) float Bs[16 * 128];  // [k][n]
    const int t  = threadIdx.x;
    const int mt = blockIdx.x;            // == s
    const int n0 = blockIdx.y * 128;
    if (t < 64) rsh[t] = X[(size_t)t * SEQ + mt];

    const int tx = t & 31, ty = t >> 5;
    const int ml = t >> 2, kq = (t & 3) * 4;
    const int vb = t >> 1, k8 = (t & 1) * 8;

    ull acc2[4][4];
#pragma unroll
    for (int rp = 0; rp < 4; rp++)
#pragma unroll
        for (int c = 0; c < 4; c++) acc2[rp][c] = 0ull;

    __syncthreads();
    const int arow = rsh[ml];

    for (int k0 = 0; k0 < EMB; k0 += 16) {
        float4 av = *(const float4*)&emb[(size_t)arow * EMB + k0 + kq];
        As[(kq + 0) * 64 + ml] = av.x;
        As[(kq + 1) * 64 + ml] = av.y;
        As[(kq + 2) * 64 + ml] = av.z;
        As[(kq + 3) * 64 + ml] = av.w;
#pragma unroll
        for (int h = 0; h < 2; h++) {
            float4 bv = *(const float4*)&W_ih[(size_t)(n0 + vb) * EMB + k0 + k8 + 4 * h];
            Bs[(k8 + 4 * h + 0) * 128 + vb] = bv.x;
            Bs[(k8 + 4 * h + 1) * 128 + vb] = bv.y;
            Bs[(k8 + 4 * h + 2) * 128 + vb] = bv.z;
            Bs[(k8 + 4 * h + 3) * 128 + vb] = bv.w;
        }
        __syncthreads();
#pragma unroll
        for (int kk = 0; kk < 16; kk++) {
            const ull* ap = (const ull*)&As[kk * 64 + ty * 8];
            ull a0 = ap[0], a1 = ap[1], a2 = ap[2], a3 = ap[3];
            float4 Wv = *(const float4*)&Bs[kk * 128 + tx * 4];
            ull wd[4] = {dup2(Wv.x), dup2(Wv.y), dup2(Wv.z), dup2(Wv.w)};
#pragma unroll
            for (int c = 0; c < 4; c++) {
                fma2(acc2[0][c], a0, wd[c]);
                fma2(acc2[1][c], a1, wd[c]);
                fma2(acc2[2][c], a2, wd[c]);
                fma2(acc2[3][c], a3, wd[c]);
            }
        }
        __syncthreads();
    }

    const int nbase = n0 + tx * 4;
    float bias[4];
#pragma unroll
    for (int c = 0; c < 4; c++) bias[c] = b_ih[nbase + c] + b_hh[nbase + c];
#pragma unroll
    for (int rp = 0; rp < 4; rp++) {
        float2 p0 = unpack2(acc2[rp][0]);
        float2 p1 = unpack2(acc2[rp][1]);
        float2 p2 = unpack2(acc2[rp][2]);
        float2 p3 = unpack2(acc2[rp][3]);
        int bl0 = ty * 8 + 2 * rp;
        float4 o0, o1;
        o0.x = p0.x + bias[0]; o0.y = p1.x + bias[1];
        o0.z = p2.x + bias[2]; o0.w = p3.x + bias[3];
        o1.x = p0.y + bias[0]; o1.y = p1.y + bias[1];
        o1.z = p2.y + bias[2]; o1.w = p3.y + bias[3];
        *(float4*)&g_xin[((size_t)mt * BATCH + bl0) * HID + nbase]     = o0;
        *(float4*)&g_xin[((size_t)mt * BATCH + bl0 + 1) * HID + nbase] = o1;
    }
}

// ===========================================================================
// K2: persistent clustered RNN, W_hh in REGISTERS.
// 16 clusters x 8 CTAs. Cluster cg owns batches [cg*4,+4); CTA rank owns
// i-rows [rank*64,+64). Thread (jseg=warp, ip=lane) holds W rows ip, ip+32
// over j in [jseg*64, +64) as 64 ull registers (loaded from GMEM once).
// Per step: FFMA2 over h (LDS.128 broadcasts from parity-buffered DSMEM
// array) -> cross-warp smem reduce -> tanh -> DSMEM push to all 8 CTAs ->
// cluster barrier. No W smem traffic, no staging copy.
// ===========================================================================
__global__ void __launch_bounds__(256, 1) __cluster_dims__(8, 1, 1)
k2_rnn(const float* __restrict__ W_hh)
{
    __shared__ __align__(16) float hbuf[2 * 4 * 512];  // [parity][b][j]
    __shared__ float red[8 * 256];                     // [jseg][b*64+i]

    const int t = threadIdx.x;
    unsigned rank;
    asm("mov.u32 %0, %%cluster_ctarank;" : "=r"(rank));
    const int cg = blockIdx.x >> 3;
    const int b0 = cg * 4;

    const int ip   = t & 31;     // i-row base (lane)
    const int jseg = t >> 5;     // warp = 64-wide j segment
    const int ob   = t >> 6;     // output batch (0..3)
    const int oi   = t & 63;     // output i (local)
    const int iglob = (int)rank * 64 + oi;

    // ---- load this thread's W_hh rows into registers (once) ----
    ull w0[32], w1[32];
    {
        const ull* wg0 = (const ull*)&W_hh[(size_t)(rank * 64 + ip) * HID + jseg * 64];
        const ull* wg1 = (const ull*)&W_hh[(size_t)(rank * 64 + ip + 32) * HID + jseg * 64];
#pragma unroll
        for (int jj = 0; jj < 32; jj++) { w0[jj] = wg0[jj]; w1[jj] = wg1[jj]; }
    }

    // peer base addresses of hbuf (DSMEM)
    unsigned hb32 = smem_u32(hbuf);
    unsigned peer[8];
#pragma unroll
    for (int r = 0; r < 8; r++)
        asm("mapa.shared::cluster.u32 %0, %1, %2;"
            : "=r"(peer[r]) : "r"(hb32), "r"(r));

    // make sure every CTA's smem is live before first DSMEM push
    asm volatile("barrier.cluster.arrive.aligned;" ::: "memory");
    asm volatile("barrier.cluster.wait.aligned;" ::: "memory");

    for (int s = 0; s < SEQ; s++) {
        float xv = __ldg(&g_xin[((size_t)s * BATCH + b0 + ob) * HID + iglob]);

        float dot = 0.f;
        if (s > 0) {
            const float* hb = hbuf + ((s - 1) & 1) * 2048;
            ull acc[8];
#pragma unroll
            for (int q = 0; q < 8; q++) acc[q] = 0ull;
#pragma unroll
            for (int q = 0; q < 16; q++) {
#pragma unroll
                for (int b = 0; b < 4; b++) {
                    // broadcast LDS.128: h[b][jseg*64 + 4q .. +3]
                    ulonglong2 h2 =
                        *(const ulonglong2*)&hb[b * 512 + jseg * 64 + q * 4];
                    fma2(acc[b],     w0[2 * q],     h2.x);
                    fma2(acc[4 + b], w1[2 * q],     h2.x);
                    fma2(acc[b],     w0[2 * q + 1], h2.y);
                    fma2(acc[4 + b], w1[2 * q + 1], h2.y);
                }
            }
#pragma unroll
            for (int b4 = 0; b4 < 4; b4++) {
                float2 pa = unpack2(acc[b4]);
                float2 pb = unpack2(acc[4 + b4]);
                red[jseg * 256 + b4 * 64 + ip]      = pa.x + pa.y;
                red[jseg * 256 + b4 * 64 + ip + 32] = pb.x + pb.y;
            }
            __syncthreads();
#pragma unroll
            for (int q = 0; q < 8; q++)
                dot += red[q * 256 + t];
        }

        float h = tanhf(xv + dot);

        // push h to every cluster CTA's parity buffer (incl. self)
        unsigned boff = (unsigned)(((s & 1) * 2048 + ob * 512 + iglob) * 4);
#pragma unroll
        for (int r = 0; r < 8; r++)
            asm volatile("st.shared::cluster.f32 [%0], %1;"
                         :: "r"(peer[r] + boff), "f"(h) : "memory");

        asm volatile("barrier.cluster.arrive.aligned;" ::: "memory");
        // off-critical-path record for K3, overlapped with the wait
        g_states[((size_t)s * BATCH + b0 + ob) * HID + iglob] = h;
        asm volatile("barrier.cluster.wait.aligned;" ::: "memory");
    }
}

// ===========================================================================
// K3: attention + feat. One CTA per batch b, 512 threads.
// ===========================================================================
__global__ void __launch_bounds__(512) k3_attn()
{
    __shared__ float lsh[512];
    __shared__ float ash[512];
    __shared__ float red[16];
    const int b = blockIdx.x;
    const int t = threadIdx.x;
    const int lane = t & 31, wid = t >> 5;

    lsh[t] = g_states[((size_t)(SEQ - 1) * BATCH + b) * HID + t];
    __syncthreads();

    for (int s = wid; s < SEQ - 1; s += 16) {
        const float* hs = &g_states[((size_t)s * BATCH + b) * HID];
        float p = 0.f;
#pragma unroll
        for (int m = 0; m < 16; m++)
            p = fmaf(hs[lane + 32 * m], lsh[lane + 32 * m], p);
#pragma unroll
        for (int o = 16; o > 0; o >>= 1) p += __shfl_down_sync(0xffffffffu, p, o);
        if (lane == 0) ash[s] = p;
    }
    __syncthreads();

    float v = (t < SEQ - 1) ? ash[t] : -3.0e38f;
    float mx = v;
#pragma unroll
    for (int o = 16; o > 0; o >>= 1) mx = fmaxf(mx, __shfl_xor_sync(0xffffffffu, mx, o));
    if (lane == 0) red[wid] = mx;
    __syncthreads();
    float m2 = red[0];
#pragma unroll
    for (int i = 1; i < 16; i++) m2 = fmaxf(m2, red[i]);
    __syncthreads();

    float e = (t < SEQ - 1) ? __expf(v - m2) : 0.f;
    float sm = e;
#pragma unroll
    for (int o = 16; o > 0; o >>= 1) sm += __shfl_xor_sync(0xffffffffu, sm, o);
    if (lane == 0) red[wid] = sm;
    __syncthreads();
    float tot = 0.f;
#pragma unroll
    for (int i = 0; i < 16; i++) tot += red[i];
    float inv = 1.f / tot;
    __syncthreads();
    if (t < SEQ - 1) ash[t] = e * inv;
    __syncthreads();

    float ctx = 0.f;
#pragma unroll 4
    for (int s = 0; s < SEQ - 1; s++)
        ctx = fmaf(ash[s], g_states[((size_t)s * BATCH + b) * HID + t], ctx);

    g_feat[b * 1024 + t]       = ctx;
    g_feat[b * 1024 + 512 + t] = lsh[t];
}

// ===========================================================================
// K4: out[b][v] = dot(feat[b], W[v]) + bias[v]. M=64, N=32000, K=1024.
// ===========================================================================
__global__ void __launch_bounds__(256) k4_out(
    const float* __restrict__ W, const float* __restrict__ bias,
    float* __restrict__ out)
{
    __shared__ __align__(16) float As[16 * 64];
    __shared__ __align__(16) float Bs[16 * 128];
    const int t  = threadIdx.x;
    const int n0 = blockIdx.x * 128;
    const int tx = t & 31, ty = t >> 5;
    const int ml = t >> 2, kq = (t & 3) * 4;
    const int vb = t >> 1, k8 = (t & 1) * 8;

    ull acc2[4][4];
#pragma unroll
    for (int rp = 0; rp < 4; rp++)
#pragma unroll
        for (int c = 0; c < 4; c++) acc2[rp][c] = 0ull;

    for (int k0 = 0; k0 < 2 * HID; k0 += 16) {
        float4 av = *(const float4*)&g_feat[(size_t)ml * 1024 + k0 + kq];
        As[(kq + 0) * 64 + ml] = av.x;
        As[(kq + 1) * 64 + ml] = av.y;
        As[(kq + 2) * 64 + ml] = av.z;
        As[(kq + 3) * 64 + ml] = av.w;
#pragma unroll
        for (int h = 0; h < 2; h++) {
            float4 bv = *(const float4*)&W[(size_t)(n0 + vb) * 1024 + k0 + k8 + 4 * h];
            Bs[(k8 + 4 * h + 0) * 128 + vb] = bv.x;
            Bs[(k8 + 4 * h + 1) * 128 + vb] = bv.y;
            Bs[(k8 + 4 * h + 2) * 128 + vb] = bv.z;
            Bs[(k8 + 4 * h + 3) * 128 + vb] = bv.w;
        }
        __syncthreads();
#pragma unroll
        for (int kk = 0; kk < 16; kk++) {
            const ull* ap = (const ull*)&As[kk * 64 + ty * 8];
            ull a0 = ap[0], a1 = ap[1], a2 = ap[2], a3 = ap[3];
            float4 Wv = *(const float4*)&Bs[kk * 128 + tx * 4];
            ull wd[4] = {dup2(Wv.x), dup2(Wv.y), dup2(Wv.z), dup2(Wv.w)};
#pragma unroll
            for (int c = 0; c < 4; c++) {
                fma2(acc2[0][c], a0, wd[c]);
                fma2(acc2[1][c], a1, wd[c]);
                fma2(acc2[2][c], a2, wd[c]);
                fma2(acc2[3][c], a3, wd[c]);
            }
        }
        __syncthreads();
    }

    const int nbase = n0 + tx * 4;
    float bv0 = bias[nbase + 0], bv1 = bias[nbase + 1];
    float bv2 = bias[nbase + 2], bv3 = bias[nbase + 3];
#pragma unroll
    for (int rp = 0; rp < 4; rp++) {
        float2 p0 = unpack2(acc2[rp][0]);
        float2 p1 = unpack2(acc2[rp][1]);
        float2 p2 = unpack2(acc2[rp][2]);
        float2 p3 = unpack2(acc2[rp][3]);
        int bb0 = ty * 8 + 2 * rp;
        float4 o0, o1;
        o0.x = p0.x + bv0; o0.y = p1.x + bv1; o0.z = p2.x + bv2; o0.w = p3.x + bv3;
        o1.x = p0.y + bv0; o1.y = p1.y + bv1; o1.z = p2.y + bv2; o1.w = p3.y + bv3;
        *(float4*)&out[(size_t)bb0 * VOCAB + nbase]       = o0;
        *(float4*)&out[(size_t)(bb0 + 1) * VOCAB + nbase] = o1;
    }
}

// ===========================================================================
extern "C" void kernel_launch(void* const* d_in, const int* in_sizes, int n_in,
                              void* d_out, int out_size) {
    (void)in_sizes; (void)n_in; (void)out_size;
    const int*   X    = (const int*)d_in[0];
    const float* emb  = (const float*)d_in[1];
    const float* W_ih = (const float*)d_in[2];
    const float* W_hh = (const float*)d_in[3];
    const float* b_ih = (const float*)d_in[4];
    const float* b_hh = (const float*)d_in[5];
    const float* W    = (const float*)d_in[6];
    const float* bias = (const float*)d_in[7];
    float* out = (float*)d_out;

    k1_xin<<<dim3(SEQ, 4), 256>>>(X, emb, W_ih, b_ih, b_hh);
    k2_rnn<<<128, 256>>>(W_hh);
    k3_attn<<<BATCH, 512>>>();
    k4_out<<<VOCAB / 128, 256>>>(W, bias, out);
}